// round 17
// baseline (speedup 1.0000x reference)
#include <cuda_runtime.h>
#include <cuda_fp16.h>
#include <cstdint>

#define D_FEAT 64
#define TILE_M 128
#define NTHREADS 256
#define K_CLUSTERS 512
#define INV_T 10.0f
#define LOG2E 1.4426950408889634f

// smem byte offsets
#define SM_G1 0            // GEMM1 B fragments (fp16, packed)  64KB
#define SM_G2 65536        // GEMM2 B fragments (fp16, packed)  64KB
#define SM_BIAS 131072     // 512 floats                        2KB
#define SM_W 133120        // W staging, 2 parity slots         32KB
#define SM_TOTAL 165888

typedef unsigned int u32;

__device__ __forceinline__ u32 s2u(const void* p) {
    u32 a;
    asm("{ .reg .u64 t; cvta.to.shared.u64 t, %1; cvt.u32.u64 %0, t; }" : "=r"(a) : "l"(p));
    return a;
}
__device__ __forceinline__ void lds128(u32 addr, u32& q0, u32& q1, u32& q2, u32& q3) {
    asm volatile("ld.shared.v4.b32 {%0,%1,%2,%3}, [%4];"
                 : "=r"(q0), "=r"(q1), "=r"(q2), "=r"(q3) : "r"(addr));
}
__device__ __forceinline__ void sts128(u32 addr, u32 q0, u32 q1, u32 q2, u32 q3) {
    asm volatile("st.shared.v4.b32 [%0], {%1,%2,%3,%4};"
                 :: "r"(addr), "r"(q0), "r"(q1), "r"(q2), "r"(q3) : "memory");
}
__device__ __forceinline__ float ex2f(float v) {
    float y; asm("ex2.approx.ftz.f32 %0, %1;" : "=f"(y) : "f"(v)); return y;
}
// pack (lo, hi) floats -> f16x2 with lo in the LOW half
__device__ __forceinline__ u32 f2h2(float lo, float hi) {
    u32 r; asm("cvt.rn.f16x2.f32 %0, %1, %2;" : "=r"(r) : "f"(hi), "f"(lo)); return r;
}
__device__ __forceinline__ float2 unh2(u32 v) {
    __half2 h = *reinterpret_cast<__half2*>(&v);
    return __half22float2(h);
}
// fp16 hi split + fp16 residual split (22 effective bits)
__device__ __forceinline__ u32 f16r(float a, float b, u32& lo) {
    const u32 h = f2h2(a, b);
    const float2 f = unh2(h);
    lo = f2h2(a - f.x, b - f.y);
    return h;
}
// D += A*B, m16n8k16 fp16 in, f32 accum
__device__ __forceinline__ void mma16816(float* d, const u32* a, u32 b0, u32 b1) {
    asm volatile("mma.sync.aligned.m16n8k16.row.col.f32.f16.f16.f32 "
                 "{%0,%1,%2,%3}, {%4,%5,%6,%7}, {%8,%9}, {%0,%1,%2,%3};"
                 : "+f"(d[0]), "+f"(d[1]), "+f"(d[2]), "+f"(d[3])
                 : "r"(a[0]), "r"(a[1]), "r"(a[2]), "r"(a[3]), "r"(b0), "r"(b1));
}

// GEMM1 of one 64-cluster sub into S (2-term fp16)
__device__ __forceinline__ void g1sub(u32 g1b, int sub, float S[8][4],
                                      const u32 Ah[4][4], const u32 Al[4][4]) {
    const u32 so1 = g1b + (u32)sub * 8192;
    #pragma unroll
    for (int s = 0; s < 4; s++) {
        const u32 base = so1 + (u32)s * 2048;
        #pragma unroll
        for (int nbp = 0; nbp < 4; nbp++) {
            u32 q0, q1, q2, q3;
            lds128(base + nbp * 512, q0, q1, q2, q3);
            mma16816(S[2 * nbp],     Ah[s], q0, q1);
            mma16816(S[2 * nbp],     Al[s], q0, q1);
            mma16816(S[2 * nbp + 1], Ah[s], q2, q3);
            mma16816(S[2 * nbp + 1], Al[s], q2, q3);
        }
    }
}
// GEMM2 of one sub, A = W read back from private smem slot (1-term fp16)
__device__ __forceinline__ void g2sub(u32 g2b, u32 wslot, int sub, float O[8][4]) {
    const u32 so2 = g2b + (u32)sub * 8192;
    #pragma unroll
    for (int t = 0; t < 4; t++) {
        u32 W[4];
        lds128(wslot + (u32)t * 512, W[0], W[1], W[2], W[3]);
        const u32 base = so2 + (u32)t * 2048;
        #pragma unroll
        for (int nbp2 = 0; nbp2 < 4; nbp2++) {
            u32 q0, q1, q2, q3;
            lds128(base + nbp2 * 512, q0, q1, q2, q3);
            mma16816(O[2 * nbp2],     W, q0, q1);
            mma16816(O[2 * nbp2 + 1], W, q2, q3);
        }
    }
}

__global__ void __launch_bounds__(NTHREADS, 1)
kmeans_hmma14_kernel(const float* __restrict__ x,
                     const float* __restrict__ centroids,
                     float* __restrict__ out,
                     int n_tiles)
{
    extern __shared__ char smem[];
    const u32 sb = s2u(smem);
    const int tid = threadIdx.x;
    const int lane = tid & 31;
    const int wid = tid >> 5;
    const int gid = lane >> 2;
    const int tg = lane & 3;
    const int m0 = wid * 16;

    const float SC = 2.0f * INV_T * LOG2E;
    const u32 g1b = sb + SM_G1 + (u32)lane * 16;
    const u32 g2b = sb + SM_G2 + (u32)lane * 16;
    // private W staging slots: [parity][wid][t][lane] x 16B
    const u32 wbase = sb + SM_W + (u32)wid * 2048 + (u32)lane * 16;

    // ---- prologue (once): fp16 fragment-packed B tables for both GEMMs + bias ----
    {
        const float4* C4 = reinterpret_cast<const float4*>(centroids);
        const float BSCALE = INV_T * LOG2E;
        #pragma unroll 1
        for (int i = tid; i < K_CLUSTERS * 16; i += NTHREADS) {   // 8192
            const float4 v = C4[i];
            const int cl = i >> 4;                 // cluster 0..511
            const int dq = i & 15;                 // float4 index in row
            float vf[4] = {v.x, v.y, v.z, v.w};
            const int sub = cl >> 6;               // 0..7
            const int nb = (cl >> 3) & 7, gids = cl & 7;
            const int nbp = nb >> 1, odd = nb & 1;
            const int rr = cl & 63, t2 = rr >> 4, q2 = rr & 15;
            const int reg2 = (q2 >> 3) & 1, tgs2 = (q2 & 7) >> 1, el2 = q2 & 1;
            #pragma unroll
            for (int e = 0; e < 4; e++) {
                const int d = 4 * dq + e;
                const __half hv = __float2half_rn(vf[e]);
                // G1: k = feat, n = cluster
                {
                    const int s = d >> 4, r = d & 15;
                    const int reg = (r >> 3) & 1, tgs = (r & 7) >> 1, el = r & 1;
                    const u32 off = (u32)(((sub * 16 + s * 4 + nbp) * 32 + gids * 4 + tgs) * 16
                                          + odd * 8 + reg * 4 + el * 2);
                    *reinterpret_cast<__half*>(smem + SM_G1 + off) = hv;
                }
                // G2: k = cluster, n = feat
                {
                    const int nb2 = d >> 3, gids2 = d & 7;
                    const int nbp2 = nb2 >> 1, odd2 = nb2 & 1;
                    const u32 off = (u32)(((sub * 16 + t2 * 4 + nbp2) * 32 + gids2 * 4 + tgs2) * 16
                                          + odd2 * 8 + reg2 * 4 + el2 * 2);
                    *reinterpret_cast<__half*>(smem + SM_G2 + off) = hv;
                }
            }
            float p = v.x * v.x + v.y * v.y + v.z * v.z + v.w * v.w;
            p += __shfl_xor_sync(0xFFFFFFFF, p, 1);
            p += __shfl_xor_sync(0xFFFFFFFF, p, 2);
            p += __shfl_xor_sync(0xFFFFFFFF, p, 4);
            p += __shfl_xor_sync(0xFFFFFFFF, p, 8);
            if ((lane & 15) == 0)
                *reinterpret_cast<float*>(smem + SM_BIAS + cl * 4) = p * BSCALE;
        }
    }
    __syncthreads();   // tables read-only from here: no further syncs needed

    // ---- tile loop: single pass over ALL 512 clusters per tile ----
    #pragma unroll 1
    for (int tile = blockIdx.x; tile < n_tiles; tile += gridDim.x) {
        // A fragments from gmem: X as fp16 hi + fp16 residual (PTX spec positions)
        u32 Ah[4][4], Al[4][4];
        {
            const float* xb = x + ((size_t)tile * TILE_M + m0 + gid) * D_FEAT;
            #pragma unroll
            for (int s = 0; s < 4; s++) {
                const int c0 = 16 * s + 2 * tg;
                const float2 v0 = *reinterpret_cast<const float2*>(xb + c0);
                const float2 v1 = *reinterpret_cast<const float2*>(xb + 8 * D_FEAT + c0);
                const float2 v2 = *reinterpret_cast<const float2*>(xb + c0 + 8);
                const float2 v3 = *reinterpret_cast<const float2*>(xb + 8 * D_FEAT + c0 + 8);
                Ah[s][0] = f16r(v0.x, v0.y, Al[s][0]);
                Ah[s][1] = f16r(v1.x, v1.y, Al[s][1]);
                Ah[s][2] = f16r(v2.x, v2.y, Al[s][2]);
                Ah[s][3] = f16r(v3.x, v3.y, Al[s][3]);
            }
        }

        float O[8][4];
        #pragma unroll
        for (int n = 0; n < 8; n++)
            #pragma unroll
            for (int e = 0; e < 4; e++) O[n][e] = 0.f;
        float sum0 = 0.f, sum1 = 0.f;
        float M0 = -1e30f, M1 = -1e30f;      // running row maxes (log2 units)
        float S[8][4];

        // epilogue: logits -> flash max -> weights -> STAGE Wh TO SMEM slot
        #define EPI_STAGE(i)                                                        \
        {                                                                           \
            _Pragma("unroll")                                                       \
            for (int nb = 0; nb < 8; nb++) {                                        \
                const int coll = (i) * 64 + nb * 8 + 2 * tg;                        \
                const float2 bb = *reinterpret_cast<const float2*>(                 \
                    smem + SM_BIAS + coll * 4);                                     \
                S[nb][0] = fmaf(S[nb][0], SC, -bb.x);                               \
                S[nb][1] = fmaf(S[nb][1], SC, -bb.y);                               \
                S[nb][2] = fmaf(S[nb][2], SC, -bb.x);                               \
                S[nb][3] = fmaf(S[nb][3], SC, -bb.y);                               \
            }                                                                       \
            float m0c = S[0][0], m1c = S[0][2];                                     \
            _Pragma("unroll")                                                       \
            for (int nb = 0; nb < 8; nb++) {                                        \
                m0c = fmaxf(m0c, fmaxf(S[nb][0], S[nb][1]));                        \
                m1c = fmaxf(m1c, fmaxf(S[nb][2], S[nb][3]));                        \
            }                                                                       \
            m0c = fmaxf(m0c, __shfl_xor_sync(0xFFFFFFFF, m0c, 1));                  \
            m0c = fmaxf(m0c, __shfl_xor_sync(0xFFFFFFFF, m0c, 2));                  \
            m1c = fmaxf(m1c, __shfl_xor_sync(0xFFFFFFFF, m1c, 1));                  \
            m1c = fmaxf(m1c, __shfl_xor_sync(0xFFFFFFFF, m1c, 2));                  \
            const float M0n = fmaxf(M0, m0c);                                       \
            const float M1n = fmaxf(M1, m1c);                                       \
            const float sc0 = ex2f(M0 - M0n);                                       \
            const float sc1 = ex2f(M1 - M1n);                                       \
            M0 = M0n; M1 = M1n;                                                     \
            sum0 *= sc0; sum1 *= sc1;                                               \
            _Pragma("unroll")                                                       \
            for (int n = 0; n < 8; n++) {                                           \
                O[n][0] *= sc0; O[n][1] *= sc0;                                     \
                O[n][2] *= sc1; O[n][3] *= sc1;                                     \
            }                                                                       \
            _Pragma("unroll")                                                       \
            for (int nb = 0; nb < 8; nb++) {                                        \
                S[nb][0] = ex2f(S[nb][0] - M0);                                     \
                S[nb][1] = ex2f(S[nb][1] - M0);                                     \
                S[nb][2] = ex2f(S[nb][2] - M1);                                     \
                S[nb][3] = ex2f(S[nb][3] - M1);                                     \
                sum0 += S[nb][0] + S[nb][1];                                        \
                sum1 += S[nb][2] + S[nb][3];                                        \
            }                                                                       \
            const u32 ws = wbase + ((u32)((i) & 1)) * 16384;                        \
            _Pragma("unroll")                                                       \
            for (int t = 0; t < 4; t++) {                                           \
                sts128(ws + (u32)t * 512,                                           \
                       f2h2(S[2*t][0],   S[2*t][1]),                                \
                       f2h2(S[2*t][2],   S[2*t][3]),                                \
                       f2h2(S[2*t+1][0], S[2*t+1][1]),                              \
                       f2h2(S[2*t+1][2], S[2*t+1][3]));                             \
            }                                                                       \
        }
        #define ZERO_S                                                              \
        { _Pragma("unroll") for (int n = 0; n < 8; n++)                             \
          { _Pragma("unroll") for (int e = 0; e < 4; e++) S[n][e] = 0.f; } }

        // pipeline prologue: sub 0
        ZERO_S;
        g1sub(g1b, 0, S, Ah, Al);
        EPI_STAGE(0);

        // steady state: GEMM1(i) || GEMM2(i-1) || epilogue(i)
        // GEMM2(i-1) reads slot (i-1)&1; epilogue(i) writes slot i&1 — no conflict,
        // and GEMM2/epilogue are data-independent so ptxas keeps HMMAs in flight
        // through the MUFU chain.
        #pragma unroll 1
        for (int i = 1; i < 8; i++) {
            ZERO_S;
            g1sub(g1b, i, S, Ah, Al);
            g2sub(g2b, wbase + ((u32)((i - 1) & 1)) * 16384, i - 1, O);
            EPI_STAGE(i);
        }
        // drain
        g2sub(g2b, wbase + 16384u, 7, O);

        #undef EPI_STAGE
        #undef ZERO_S

        // normalize + single store (scale factors cancel between O and sum)
        sum0 += __shfl_xor_sync(0xFFFFFFFF, sum0, 1);
        sum0 += __shfl_xor_sync(0xFFFFFFFF, sum0, 2);
        sum1 += __shfl_xor_sync(0xFFFFFFFF, sum1, 1);
        sum1 += __shfl_xor_sync(0xFFFFFFFF, sum1, 2);
        const float inv0 = __frcp_rn(sum0);
        const float inv1 = __frcp_rn(sum1);

        float* op = out + ((size_t)tile * TILE_M) * D_FEAT;
        const int r0 = m0 + gid;
        const int r1 = r0 + 8;
        #pragma unroll
        for (int n = 0; n < 8; n++) {
            const int col = 8 * n + 2 * tg;
            *reinterpret_cast<float2*>(op + r0 * D_FEAT + col) =
                make_float2(O[n][0] * inv0, O[n][1] * inv0);
            *reinterpret_cast<float2*>(op + r1 * D_FEAT + col) =
                make_float2(O[n][2] * inv1, O[n][3] * inv1);
        }
    }
}

extern "C" void kernel_launch(void* const* d_in, const int* in_sizes, int n_in,
                              void* d_out, int out_size)
{
    const float* x = (const float*)d_in[0];
    const float* centroids = (const float*)d_in[1];
    float* out = (float*)d_out;

    const int n_points = in_sizes[0] / D_FEAT;   // 131072
    const int n_tiles = n_points / TILE_M;       // 1024

    static bool attr_set = false;
    if (!attr_set) {
        cudaFuncSetAttribute(kmeans_hmma14_kernel,
                             cudaFuncAttributeMaxDynamicSharedMemorySize, SM_TOTAL);
        attr_set = true;
    }

    const int grid = (n_tiles < 148) ? n_tiles : 148;
    kmeans_hmma14_kernel<<<grid, NTHREADS, SM_TOTAL>>>(x, centroids, out, n_tiles);
}